// round 9
// baseline (speedup 1.0000x reference)
#include <cuda_runtime.h>
#include <cuda_bf16.h>
#include <cstdint>

// ============================ problem constants ============================
constexpr int Bn = 4096;
constexpr int Dd = 512;
constexpr int Nn = 2 * Bn;              // 8192
constexpr int NB = Nn / 128;            // 64 row/col blocks
constexpr int NPAIRS = NB * (NB + 1) / 2;  // 2080 CTAs (lower triangle incl diag)

constexpr float SCALE = 256.0f;                       // int8 quant scale
constexpr float INV_SS_T = 2.0f / (256.0f * 256.0f);  // (1/S^2)/TEMP

constexpr int BK = 64;                  // K bytes (= int8 elems) per stage
constexpr int KITERS = Dd / BK;         // 8
constexpr int STAGES = 4;
constexpr int LDSB = 80;                // padded row stride in bytes
constexpr int TILE_BYTES = 128 * LDSB;           // 10240 per operand tile
constexpr int STAGE_BYTES = 2 * TILE_BYTES;      // 20480
constexpr int SROW_OFF = STAGES * STAGE_BYTES;   // 81920
constexpr int SCOL_OFF = SROW_OFF + 128 * 4;
constexpr int SMEM_BYTES = SCOL_OFF + 128 * 4;   // 82944

// ============================ device scratch ============================
__device__ __align__(16) uint8_t g_zn8[(size_t)Nn * Dd];  // 4 MB, s8
__device__ float g_rowsum[Nn];
__device__ float g_pos[Nn];

// ============================ PTX helpers ============================
__device__ __forceinline__ uint32_t smem_u32(const void* p) {
    uint32_t a;
    asm("{ .reg .u64 t; cvta.to.shared.u64 t, %1; cvt.u32.u64 %0, t; }" : "=r"(a) : "l"(p));
    return a;
}

__device__ __forceinline__ void cp_async16(uint32_t sdst, const void* gsrc) {
    asm volatile("cp.async.cg.shared.global [%0], [%1], 16;" :: "r"(sdst), "l"(gsrc));
}
__device__ __forceinline__ void cp_commit() {
    asm volatile("cp.async.commit_group;" ::: "memory");
}
template <int N>
__device__ __forceinline__ void cp_wait() {
    asm volatile("cp.async.wait_group %0;" :: "n"(N) : "memory");
}

__device__ __forceinline__ void ldmatrix_x4(uint32_t& r0, uint32_t& r1, uint32_t& r2,
                                            uint32_t& r3, uint32_t addr) {
    asm volatile("ldmatrix.sync.aligned.m8n8.x4.shared.b16 {%0,%1,%2,%3}, [%4];"
                 : "=r"(r0), "=r"(r1), "=r"(r2), "=r"(r3) : "r"(addr));
}

// int8 IMMA: m16n8k32, row.col, s32 accum
__device__ __forceinline__ void mma_s8(int* c, const uint32_t* a, const uint32_t* b) {
    asm volatile(
        "mma.sync.aligned.m16n8k32.row.col.s32.s8.s8.s32 "
        "{%0,%1,%2,%3}, {%4,%5,%6,%7}, {%8,%9}, {%0,%1,%2,%3};"
        : "+r"(c[0]), "+r"(c[1]), "+r"(c[2]), "+r"(c[3])
        : "r"(a[0]), "r"(a[1]), "r"(a[2]), "r"(a[3]), "r"(b[0]), "r"(b[1]));
}

// float -> rounded int8 (values bounded well inside [-127,127])
__device__ __forceinline__ uint32_t pack_s8x4(float a, float b, float c, float d) {
    int ia = __float2int_rn(a);
    int ib = __float2int_rn(b);
    int ic = __float2int_rn(c);
    int id = __float2int_rn(d);
    return (uint32_t)(ia & 255) | ((uint32_t)(ib & 255) << 8) |
           ((uint32_t)(ic & 255) << 16) | ((uint32_t)(id & 255) << 24);
}

// ============================ kernel 1: normalize + int8 quantize ============================
// Warp per row: 256 threads = 8 warps = 8 rows per block.
__global__ __launch_bounds__(256) void normalize_kernel(const float* __restrict__ zi,
                                                        const float* __restrict__ zj) {
    int w = threadIdx.x >> 5;
    int lane = threadIdx.x & 31;
    int row = blockIdx.x * 8 + w;
    const float* src = (row < Bn) ? (zi + (size_t)row * Dd) : (zj + (size_t)(row - Bn) * Dd);
    const float4* src4 = reinterpret_cast<const float4*>(src);
    float4 x0 = src4[lane * 4 + 0];
    float4 x1 = src4[lane * 4 + 1];
    float4 x2 = src4[lane * 4 + 2];
    float4 x3 = src4[lane * 4 + 3];
    float ss = x0.x * x0.x + x0.y * x0.y + x0.z * x0.z + x0.w * x0.w
             + x1.x * x1.x + x1.y * x1.y + x1.z * x1.z + x1.w * x1.w
             + x2.x * x2.x + x2.y * x2.y + x2.z * x2.z + x2.w * x2.w
             + x3.x * x3.x + x3.y * x3.y + x3.z * x3.z + x3.w * x3.w;
    #pragma unroll
    for (int o = 16; o > 0; o >>= 1) ss += __shfl_xor_sync(0xFFFFFFFFu, ss, o);
    float inv = rsqrtf(fmaxf(ss, 1e-16f)) * SCALE;
    uint4 outv;
    outv.x = pack_s8x4(x0.x * inv, x0.y * inv, x0.z * inv, x0.w * inv);
    outv.y = pack_s8x4(x1.x * inv, x1.y * inv, x1.z * inv, x1.w * inv);
    outv.z = pack_s8x4(x2.x * inv, x2.y * inv, x2.z * inv, x2.w * inv);
    outv.w = pack_s8x4(x3.x * inv, x3.y * inv, x3.z * inv, x3.w * inv);
    reinterpret_cast<uint4*>(g_zn8 + (size_t)row * Dd)[lane] = outv;
    if (lane == 0) g_rowsum[row] = 0.0f;
}

// ============================ kernel 2: symmetric Gram + sum-exp (int8) ============================
// One CTA per block pair (bi >= bj). 128 threads = 4 warps in 2x2; warp tile 64x64.
__global__ __launch_bounds__(128, 2) void simclr_main_kernel() {
    extern __shared__ char smem[];
    const uint32_t sbase = smem_u32(smem);
    float* srow = reinterpret_cast<float*>(smem + SROW_OFF);
    float* scol = reinterpret_cast<float*>(smem + SCOL_OFF);

    const int tid = threadIdx.x;
    const int wid = tid >> 5;
    const int lane = tid & 31;
    const int wr = wid >> 1;        // warp row 0..1
    const int wc = wid & 1;         // warp col 0..1
    const int g = lane >> 2;        // accum row group
    const int tg = lane & 3;        // accum col group

    // linear pair index -> (bi, bj), bj <= bi
    int p = blockIdx.x;
    int bi = (int)((sqrtf(8.0f * (float)p + 1.0f) - 1.0f) * 0.5f);
    while ((bi + 1) * (bi + 2) / 2 <= p) bi++;
    while (bi * (bi + 1) / 2 > p) bi--;
    int bj = p - bi * (bi + 1) / 2;

    const int arow0 = bi * 128;
    const int brow0 = bj * 128;

    srow[tid] = 0.0f;
    scol[tid] = 0.0f;

    // -------- cp.async stage loader: 1024 x 16B per stage, 8 per thread --------
    auto issue_stage = [&](int stage, int k0) {
        #pragma unroll
        for (int i = 0; i < 8; i++) {
            int idx = tid + (i << 7);
            int tile = idx >> 9;                 // 0 = A, 1 = B
            int r = (idx >> 2) & 127;
            int s = idx & 3;
            int grow = (tile ? brow0 : arow0) + r;
            const uint8_t* gp = g_zn8 + (size_t)grow * Dd + (size_t)(k0 + s * 16);
            uint32_t sd = sbase + (uint32_t)(stage * STAGE_BYTES + tile * TILE_BYTES +
                                             r * LDSB + s * 16);
            cp_async16(sd, gp);
        }
    };

    issue_stage(0, 0);  cp_commit();
    issue_stage(1, BK); cp_commit();
    issue_stage(2, 2 * BK); cp_commit();

    int acc[4][8][4];   // 128 s32 accumulators: 64 rows x 64 cols per warp
    #pragma unroll
    for (int mi = 0; mi < 4; mi++)
        #pragma unroll
        for (int ni = 0; ni < 8; ni++)
            #pragma unroll
            for (int r = 0; r < 4; r++) acc[mi][ni][r] = 0;

    // -------- mainloop --------
    #pragma unroll 1
    for (int kt = 0; kt < KITERS; kt++) {
        cp_wait<2>();
        __syncthreads();

        if (kt + 3 < KITERS) issue_stage((kt + 3) % STAGES, (kt + 3) * BK);
        cp_commit();

        const uint32_t As = sbase + (uint32_t)((kt % STAGES) * STAGE_BYTES);
        const uint32_t Bs = As + TILE_BYTES;

        #pragma unroll
        for (int kk = 0; kk < 2; kk++) {
            uint32_t afr[4][4];
            #pragma unroll
            for (int mi = 0; mi < 4; mi++) {
                uint32_t addr = As +
                    (uint32_t)((wr * 64 + mi * 16 + (lane & 15)) * LDSB +
                               kk * 32 + ((lane >> 4) << 4));
                ldmatrix_x4(afr[mi][0], afr[mi][1], afr[mi][2], afr[mi][3], addr);
            }
            uint32_t bfr[8][2];
            #pragma unroll
            for (int h = 0; h < 4; h++) {
                uint32_t addr = Bs +
                    (uint32_t)((wc * 64 + h * 16 + ((lane >> 4) << 3) + (lane & 7)) * LDSB +
                               kk * 32 + (((lane >> 3) & 1) << 4));
                uint32_t r0, r1, r2, r3;
                ldmatrix_x4(r0, r1, r2, r3, addr);
                bfr[2 * h][0] = r0; bfr[2 * h][1] = r1;
                bfr[2 * h + 1][0] = r2; bfr[2 * h + 1][1] = r3;
            }
            #pragma unroll
            for (int mi = 0; mi < 4; mi++)
                #pragma unroll
                for (int ni = 0; ni < 8; ni++)
                    mma_s8(acc[mi][ni], afr[mi], bfr[ni]);
        }
    }

    // -------- epilogue: exp + symmetric row/col credit --------
    const bool diag = (bi == bj);
    const bool posTile = (bi - bj == 32);
    float csum[8][2];
    #pragma unroll
    for (int ni = 0; ni < 8; ni++) { csum[ni][0] = 0.0f; csum[ni][1] = 0.0f; }

    #pragma unroll
    for (int mi = 0; mi < 4; mi++) {
        float rs0 = 0.0f, rs1 = 0.0f;
        int rowt0 = wr * 64 + mi * 16 + g;
        #pragma unroll
        for (int ni = 0; ni < 8; ni++) {
            int colt0 = wc * 64 + ni * 8 + tg * 2;
            #pragma unroll
            for (int r = 0; r < 4; r++) {
                float v = (float)acc[mi][ni][r] * INV_SS_T;
                int rowt = rowt0 + ((r >> 1) << 3);
                int colt = colt0 + (r & 1);
                float e = __expf(v);
                if (diag && rowt == colt) e = 0.0f;
                if (posTile && rowt == colt) {
                    g_pos[arow0 + rowt] = v;
                    g_pos[brow0 + colt] = v;
                }
                if (r >> 1) rs1 += e; else rs0 += e;
                csum[ni][r & 1] += e;
            }
        }
        rs0 += __shfl_xor_sync(0xFFFFFFFFu, rs0, 1);
        rs0 += __shfl_xor_sync(0xFFFFFFFFu, rs0, 2);
        rs1 += __shfl_xor_sync(0xFFFFFFFFu, rs1, 1);
        rs1 += __shfl_xor_sync(0xFFFFFFFFu, rs1, 2);
        if (tg == 0) {
            atomicAdd(&srow[rowt0], rs0);
            atomicAdd(&srow[rowt0 + 8], rs1);
        }
    }
    if (!diag) {
        #pragma unroll
        for (int ni = 0; ni < 8; ni++)
            #pragma unroll
            for (int par = 0; par < 2; par++) {
                float c = csum[ni][par];
                c += __shfl_xor_sync(0xFFFFFFFFu, c, 4);
                c += __shfl_xor_sync(0xFFFFFFFFu, c, 8);
                c += __shfl_xor_sync(0xFFFFFFFFu, c, 16);
                if (g == 0) atomicAdd(&scol[wc * 64 + ni * 8 + tg * 2 + par], c);
            }
    }

    __syncthreads();
    atomicAdd(&g_rowsum[arow0 + tid], srow[tid]);
    if (!diag) atomicAdd(&g_rowsum[brow0 + tid], scol[tid]);
}

// ============================ kernel 3: finalize ============================
__global__ __launch_bounds__(1024) void finalize_kernel(float* __restrict__ out) {
    int t = threadIdx.x;
    double acc = 0.0;
    for (int i = t; i < Nn; i += 1024)
        acc += (double)(logf(g_rowsum[i]) - g_pos[i]);
    __shared__ double s[1024];
    s[t] = acc;
    __syncthreads();
    for (int o = 512; o > 0; o >>= 1) {
        if (t < o) s[t] += s[t + o];
        __syncthreads();
    }
    if (t == 0) out[0] = (float)(s[0] / (double)Nn);
}

// ============================ launch ============================
extern "C" void kernel_launch(void* const* d_in, const int* in_sizes, int n_in,
                              void* d_out, int out_size) {
    (void)in_sizes; (void)n_in; (void)out_size;
    const float* zi = (const float*)d_in[0];
    const float* zj = (const float*)d_in[1];
    float* out = (float*)d_out;

    static int smem_set = 0;
    if (!smem_set) {
        cudaFuncSetAttribute(simclr_main_kernel,
                             cudaFuncAttributeMaxDynamicSharedMemorySize, SMEM_BYTES);
        smem_set = 1;
    }

    normalize_kernel<<<Nn / 8, 256>>>(zi, zj);
    simclr_main_kernel<<<NPAIRS, 128, SMEM_BYTES>>>();
    finalize_kernel<<<1, 1024>>>(out);
}

// round 10
// speedup vs baseline: 1.5337x; 1.5337x over previous
#include <cuda_runtime.h>
#include <cuda_bf16.h>
#include <cstdint>

// ============================ problem constants ============================
constexpr int Bn = 4096;
constexpr int Dd = 512;
constexpr int Nn = 2 * Bn;              // 8192
constexpr int NB = Nn / 128;            // 64 row/col blocks
constexpr int NPAIRS = NB * (NB + 1) / 2;  // 2080 CTAs (lower triangle incl diag)

constexpr float SCALE = 256.0f;                       // fp8 quant scale
constexpr float INV_SS_T = 2.0f / (256.0f * 256.0f);  // (1/S^2)/TEMP

constexpr int BK = 64;                  // K bytes (= fp8 elems) per stage
constexpr int KITERS = Dd / BK;         // 8
constexpr int STAGES = 3;
constexpr int LDSB = 80;                // padded row stride in bytes
constexpr int TILE_BYTES = 128 * LDSB;           // 10240 per operand tile
constexpr int STAGE_BYTES = 2 * TILE_BYTES;      // 20480
constexpr int SROW_OFF = STAGES * STAGE_BYTES;   // 61440
constexpr int SCOL_OFF = SROW_OFF + 128 * 4;
constexpr int SMEM_BYTES = SCOL_OFF + 128 * 4;   // 62464

// ============================ device scratch ============================
__device__ __align__(16) uint8_t g_zn8[(size_t)Nn * Dd];  // 4 MB, e4m3
__device__ float g_rowsum[Nn];
__device__ float g_pos[Nn];

// ============================ PTX helpers ============================
__device__ __forceinline__ uint32_t smem_u32(const void* p) {
    uint32_t a;
    asm("{ .reg .u64 t; cvta.to.shared.u64 t, %1; cvt.u32.u64 %0, t; }" : "=r"(a) : "l"(p));
    return a;
}

__device__ __forceinline__ void cp_async16(uint32_t sdst, const void* gsrc) {
    asm volatile("cp.async.cg.shared.global [%0], [%1], 16;" :: "r"(sdst), "l"(gsrc));
}
__device__ __forceinline__ void cp_commit() {
    asm volatile("cp.async.commit_group;" ::: "memory");
}
template <int N>
__device__ __forceinline__ void cp_wait() {
    asm volatile("cp.async.wait_group %0;" :: "n"(N) : "memory");
}

__device__ __forceinline__ void ldmatrix_x4(uint32_t& r0, uint32_t& r1, uint32_t& r2,
                                            uint32_t& r3, uint32_t addr) {
    asm volatile("ldmatrix.sync.aligned.m8n8.x4.shared.b16 {%0,%1,%2,%3}, [%4];"
                 : "=r"(r0), "=r"(r1), "=r"(r2), "=r"(r3) : "r"(addr));
}

// fp8 e4m3 MMA: m16n8k32, row.col, f32 accum (fastest measured path)
__device__ __forceinline__ void mma_fp8(float* c, const uint32_t* a, const uint32_t* b) {
    asm volatile(
        "mma.sync.aligned.m16n8k32.row.col.f32.e4m3.e4m3.f32 "
        "{%0,%1,%2,%3}, {%4,%5,%6,%7}, {%8,%9}, {%0,%1,%2,%3};"
        : "+f"(c[0]), "+f"(c[1]), "+f"(c[2]), "+f"(c[3])
        : "r"(a[0]), "r"(a[1]), "r"(a[2]), "r"(a[3]), "r"(b[0]), "r"(b[1]));
}

// pack 2 floats -> 2 e4m3 bytes (lo = 2nd operand)
__device__ __forceinline__ uint16_t pack_e4m3x2(float hi, float lo) {
    uint16_t d;
    asm("cvt.rn.satfinite.e4m3x2.f32 %0, %1, %2;" : "=h"(d) : "f"(hi), "f"(lo));
    return d;
}

// ============================ kernel 1: normalize + fp8 quantize ============================
// Warp per row: 256 threads = 8 warps = 8 rows per block.
__global__ __launch_bounds__(256) void normalize_kernel(const float* __restrict__ zi,
                                                        const float* __restrict__ zj) {
    int w = threadIdx.x >> 5;
    int lane = threadIdx.x & 31;
    int row = blockIdx.x * 8 + w;
    const float* src = (row < Bn) ? (zi + (size_t)row * Dd) : (zj + (size_t)(row - Bn) * Dd);
    const float4* src4 = reinterpret_cast<const float4*>(src);
    float4 x0 = src4[lane * 4 + 0];
    float4 x1 = src4[lane * 4 + 1];
    float4 x2 = src4[lane * 4 + 2];
    float4 x3 = src4[lane * 4 + 3];
    float ss = x0.x * x0.x + x0.y * x0.y + x0.z * x0.z + x0.w * x0.w
             + x1.x * x1.x + x1.y * x1.y + x1.z * x1.z + x1.w * x1.w
             + x2.x * x2.x + x2.y * x2.y + x2.z * x2.z + x2.w * x2.w
             + x3.x * x3.x + x3.y * x3.y + x3.z * x3.z + x3.w * x3.w;
    #pragma unroll
    for (int o = 16; o > 0; o >>= 1) ss += __shfl_xor_sync(0xFFFFFFFFu, ss, o);
    float inv = rsqrtf(fmaxf(ss, 1e-16f)) * SCALE;
    uint4 outv;
    outv.x = (uint32_t)pack_e4m3x2(x0.y * inv, x0.x * inv) |
             ((uint32_t)pack_e4m3x2(x0.w * inv, x0.z * inv) << 16);
    outv.y = (uint32_t)pack_e4m3x2(x1.y * inv, x1.x * inv) |
             ((uint32_t)pack_e4m3x2(x1.w * inv, x1.z * inv) << 16);
    outv.z = (uint32_t)pack_e4m3x2(x2.y * inv, x2.x * inv) |
             ((uint32_t)pack_e4m3x2(x2.w * inv, x2.z * inv) << 16);
    outv.w = (uint32_t)pack_e4m3x2(x3.y * inv, x3.x * inv) |
             ((uint32_t)pack_e4m3x2(x3.w * inv, x3.z * inv) << 16);
    reinterpret_cast<uint4*>(g_zn8 + (size_t)row * Dd)[lane] = outv;
    if (lane == 0) g_rowsum[row] = 0.0f;
}

// ============================ kernel 2: symmetric Gram + sum-exp (fp8) ============================
// One CTA per block pair (bi >= bj). 128 threads = 4 warps in 2x2; warp tile 64x64.
// __launch_bounds__(128, 3): occupancy 3 kills the 8th wave (2080/444 -> 5 rounds vs 8).
__global__ __launch_bounds__(128, 3) void simclr_main_kernel() {
    extern __shared__ char smem[];
    const uint32_t sbase = smem_u32(smem);
    float* srow = reinterpret_cast<float*>(smem + SROW_OFF);
    float* scol = reinterpret_cast<float*>(smem + SCOL_OFF);

    const int tid = threadIdx.x;
    const int wid = tid >> 5;
    const int lane = tid & 31;
    const int wr = wid >> 1;        // warp row 0..1
    const int wc = wid & 1;         // warp col 0..1
    const int g = lane >> 2;        // accum row group
    const int tg = lane & 3;        // accum col group

    // linear pair index -> (bi, bj), bj <= bi
    int p = blockIdx.x;
    int bi = (int)((sqrtf(8.0f * (float)p + 1.0f) - 1.0f) * 0.5f);
    while ((bi + 1) * (bi + 2) / 2 <= p) bi++;
    while (bi * (bi + 1) / 2 > p) bi--;
    int bj = p - bi * (bi + 1) / 2;

    const int arow0 = bi * 128;
    const int brow0 = bj * 128;

    srow[tid] = 0.0f;
    scol[tid] = 0.0f;

    // -------- cp.async stage loader: 1024 x 16B per stage, 8 per thread --------
    auto issue_stage = [&](int stage, int k0) {
        #pragma unroll
        for (int i = 0; i < 8; i++) {
            int idx = tid + (i << 7);
            int tile = idx >> 9;                 // 0 = A, 1 = B
            int r = (idx >> 2) & 127;
            int s = idx & 3;
            int grow = (tile ? brow0 : arow0) + r;
            const uint8_t* gp = g_zn8 + (size_t)grow * Dd + (size_t)(k0 + s * 16);
            uint32_t sd = sbase + (uint32_t)(stage * STAGE_BYTES + tile * TILE_BYTES +
                                             r * LDSB + s * 16);
            cp_async16(sd, gp);
        }
    };

    issue_stage(0, 0);  cp_commit();
    issue_stage(1, BK); cp_commit();

    float acc[4][8][4];   // 128 f32 accumulators: 64 rows x 64 cols per warp
    #pragma unroll
    for (int mi = 0; mi < 4; mi++)
        #pragma unroll
        for (int ni = 0; ni < 8; ni++)
            #pragma unroll
            for (int r = 0; r < 4; r++) acc[mi][ni][r] = 0.0f;

    // -------- mainloop --------
    #pragma unroll 1
    for (int kt = 0; kt < KITERS; kt++) {
        cp_wait<1>();
        __syncthreads();

        if (kt + 2 < KITERS) issue_stage((kt + 2) % STAGES, (kt + 2) * BK);
        cp_commit();

        const uint32_t As = sbase + (uint32_t)((kt % STAGES) * STAGE_BYTES);
        const uint32_t Bs = As + TILE_BYTES;

        #pragma unroll
        for (int kk = 0; kk < 2; kk++) {
            uint32_t afr[4][4];
            #pragma unroll
            for (int mi = 0; mi < 4; mi++) {
                uint32_t addr = As +
                    (uint32_t)((wr * 64 + mi * 16 + (lane & 15)) * LDSB +
                               kk * 32 + ((lane >> 4) << 4));
                ldmatrix_x4(afr[mi][0], afr[mi][1], afr[mi][2], afr[mi][3], addr);
            }
            uint32_t bfr[8][2];
            #pragma unroll
            for (int h = 0; h < 4; h++) {
                uint32_t addr = Bs +
                    (uint32_t)((wc * 64 + h * 16 + ((lane >> 4) << 3) + (lane & 7)) * LDSB +
                               kk * 32 + (((lane >> 3) & 1) << 4));
                uint32_t r0, r1, r2, r3;
                ldmatrix_x4(r0, r1, r2, r3, addr);
                bfr[2 * h][0] = r0; bfr[2 * h][1] = r1;
                bfr[2 * h + 1][0] = r2; bfr[2 * h + 1][1] = r3;
            }
            #pragma unroll
            for (int mi = 0; mi < 4; mi++)
                #pragma unroll
                for (int ni = 0; ni < 8; ni++)
                    mma_fp8(acc[mi][ni], afr[mi], bfr[ni]);
        }
    }

    // -------- epilogue: exp + symmetric row/col credit --------
    const bool diag = (bi == bj);
    const bool posTile = (bi - bj == 32);
    float csum[8][2];
    #pragma unroll
    for (int ni = 0; ni < 8; ni++) { csum[ni][0] = 0.0f; csum[ni][1] = 0.0f; }

    #pragma unroll
    for (int mi = 0; mi < 4; mi++) {
        float rs0 = 0.0f, rs1 = 0.0f;
        int rowt0 = wr * 64 + mi * 16 + g;
        #pragma unroll
        for (int ni = 0; ni < 8; ni++) {
            int colt0 = wc * 64 + ni * 8 + tg * 2;
            #pragma unroll
            for (int r = 0; r < 4; r++) {
                float v = acc[mi][ni][r] * INV_SS_T;
                int rowt = rowt0 + ((r >> 1) << 3);
                int colt = colt0 + (r & 1);
                float e = __expf(v);
                if (diag && rowt == colt) e = 0.0f;
                if (posTile && rowt == colt) {
                    g_pos[arow0 + rowt] = v;
                    g_pos[brow0 + colt] = v;
                }
                if (r >> 1) rs1 += e; else rs0 += e;
                csum[ni][r & 1] += e;
            }
        }
        rs0 += __shfl_xor_sync(0xFFFFFFFFu, rs0, 1);
        rs0 += __shfl_xor_sync(0xFFFFFFFFu, rs0, 2);
        rs1 += __shfl_xor_sync(0xFFFFFFFFu, rs1, 1);
        rs1 += __shfl_xor_sync(0xFFFFFFFFu, rs1, 2);
        if (tg == 0) {
            atomicAdd(&srow[rowt0], rs0);
            atomicAdd(&srow[rowt0 + 8], rs1);
        }
    }
    if (!diag) {
        #pragma unroll
        for (int ni = 0; ni < 8; ni++)
            #pragma unroll
            for (int par = 0; par < 2; par++) {
                float c = csum[ni][par];
                c += __shfl_xor_sync(0xFFFFFFFFu, c, 4);
                c += __shfl_xor_sync(0xFFFFFFFFu, c, 8);
                c += __shfl_xor_sync(0xFFFFFFFFu, c, 16);
                if (g == 0) atomicAdd(&scol[wc * 64 + ni * 8 + tg * 2 + par], c);
            }
    }

    __syncthreads();
    atomicAdd(&g_rowsum[arow0 + tid], srow[tid]);
    if (!diag) atomicAdd(&g_rowsum[brow0 + tid], scol[tid]);
}

// ============================ kernel 3: finalize ============================
__global__ __launch_bounds__(1024) void finalize_kernel(float* __restrict__ out) {
    int t = threadIdx.x;
    double acc = 0.0;
    for (int i = t; i < Nn; i += 1024)
        acc += (double)(logf(g_rowsum[i]) - g_pos[i]);
    __shared__ double s[1024];
    s[t] = acc;
    __syncthreads();
    for (int o = 512; o > 0; o >>= 1) {
        if (t < o) s[t] += s[t + o];
        __syncthreads();
    }
    if (t == 0) out[0] = (float)(s[0] / (double)Nn);
}

// ============================ launch ============================
extern "C" void kernel_launch(void* const* d_in, const int* in_sizes, int n_in,
                              void* d_out, int out_size) {
    (void)in_sizes; (void)n_in; (void)out_size;
    const float* zi = (const float*)d_in[0];
    const float* zj = (const float*)d_in[1];
    float* out = (float*)d_out;

    static int smem_set = 0;
    if (!smem_set) {
        cudaFuncSetAttribute(simclr_main_kernel,
                             cudaFuncAttributeMaxDynamicSharedMemorySize, SMEM_BYTES);
        smem_set = 1;
    }

    normalize_kernel<<<Nn / 8, 256>>>(zi, zj);
    simclr_main_kernel<<<NPAIRS, 128, SMEM_BYTES>>>();
    finalize_kernel<<<1, 1024>>>(out);
}

// round 13
// speedup vs baseline: 2.1060x; 1.3731x over previous
#include <cuda_runtime.h>
#include <cuda_bf16.h>
#include <cstdint>

// ============================ problem constants ============================
constexpr int Bn = 4096;
constexpr int Dd = 512;
constexpr int Nn = 2 * Bn;              // 8192
constexpr int NB = Nn / 128;            // 64 row/col blocks
constexpr int NPAIRS = NB * (NB + 1) / 2;  // 2080 CTAs (lower triangle incl diag)

constexpr float SCALE = 256.0f;                       // fp8 quant scale
constexpr float INV_SS_T = 2.0f / (256.0f * 256.0f);  // (1/S^2)/TEMP

constexpr int BK = 64;                  // K bytes (= fp8 elems) per stage
constexpr int KITERS = Dd / BK;         // 8
constexpr int STAGES = 4;
constexpr int LDSB = 80;                // padded row stride in bytes
constexpr int TILE_BYTES = 128 * LDSB;           // 10240 per operand tile
constexpr int STAGE_BYTES = 2 * TILE_BYTES;      // 20480
constexpr int SROW_OFF = STAGES * STAGE_BYTES;   // 81920
constexpr int SCOL_OFF = SROW_OFF + 128 * 4;
constexpr int SMEM_BYTES = SCOL_OFF + 128 * 4;   // 82944

// ============================ device scratch ============================
__device__ __align__(16) uint8_t g_zn8[(size_t)Nn * Dd];  // 4 MB, e4m3
__device__ float g_rowsum[Nn];
__device__ float g_pos[Nn];

// ============================ PTX helpers ============================
__device__ __forceinline__ uint32_t smem_u32(const void* p) {
    uint32_t a;
    asm("{ .reg .u64 t; cvta.to.shared.u64 t, %1; cvt.u32.u64 %0, t; }" : "=r"(a) : "l"(p));
    return a;
}

__device__ __forceinline__ void cp_async16(uint32_t sdst, const void* gsrc) {
    asm volatile("cp.async.cg.shared.global [%0], [%1], 16;" :: "r"(sdst), "l"(gsrc));
}
__device__ __forceinline__ void cp_commit() {
    asm volatile("cp.async.commit_group;" ::: "memory");
}
template <int N>
__device__ __forceinline__ void cp_wait() {
    asm volatile("cp.async.wait_group %0;" :: "n"(N) : "memory");
}

__device__ __forceinline__ void ldmatrix_x4(uint32_t& r0, uint32_t& r1, uint32_t& r2,
                                            uint32_t& r3, uint32_t addr) {
    asm volatile("ldmatrix.sync.aligned.m8n8.x4.shared.b16 {%0,%1,%2,%3}, [%4];"
                 : "=r"(r0), "=r"(r1), "=r"(r2), "=r"(r3) : "r"(addr));
}

// fp8 e4m3 MMA: m16n8k32, row.col, f32 accum (fastest measured path)
__device__ __forceinline__ void mma_fp8(float* c, const uint32_t* a, const uint32_t* b) {
    asm volatile(
        "mma.sync.aligned.m16n8k32.row.col.f32.e4m3.e4m3.f32 "
        "{%0,%1,%2,%3}, {%4,%5,%6,%7}, {%8,%9}, {%0,%1,%2,%3};"
        : "+f"(c[0]), "+f"(c[1]), "+f"(c[2]), "+f"(c[3])
        : "r"(a[0]), "r"(a[1]), "r"(a[2]), "r"(a[3]), "r"(b[0]), "r"(b[1]));
}

// pack 2 floats -> 2 e4m3 bytes (lo = 2nd operand)
__device__ __forceinline__ uint16_t pack_e4m3x2(float hi, float lo) {
    uint16_t d;
    asm("cvt.rn.satfinite.e4m3x2.f32 %0, %1, %2;" : "=h"(d) : "f"(hi), "f"(lo));
    return d;
}

// ============================ kernel 1: normalize + fp8 quantize ============================
// Warp per row: 256 threads = 8 warps = 8 rows per block.
__global__ __launch_bounds__(256) void normalize_kernel(const float* __restrict__ zi,
                                                        const float* __restrict__ zj) {
    int w = threadIdx.x >> 5;
    int lane = threadIdx.x & 31;
    int row = blockIdx.x * 8 + w;
    const float* src = (row < Bn) ? (zi + (size_t)row * Dd) : (zj + (size_t)(row - Bn) * Dd);
    const float4* src4 = reinterpret_cast<const float4*>(src);
    float4 x0 = src4[lane * 4 + 0];
    float4 x1 = src4[lane * 4 + 1];
    float4 x2 = src4[lane * 4 + 2];
    float4 x3 = src4[lane * 4 + 3];
    float ss = x0.x * x0.x + x0.y * x0.y + x0.z * x0.z + x0.w * x0.w
             + x1.x * x1.x + x1.y * x1.y + x1.z * x1.z + x1.w * x1.w
             + x2.x * x2.x + x2.y * x2.y + x2.z * x2.z + x2.w * x2.w
             + x3.x * x3.x + x3.y * x3.y + x3.z * x3.z + x3.w * x3.w;
    #pragma unroll
    for (int o = 16; o > 0; o >>= 1) ss += __shfl_xor_sync(0xFFFFFFFFu, ss, o);
    float inv = rsqrtf(fmaxf(ss, 1e-16f)) * SCALE;
    uint4 outv;
    outv.x = (uint32_t)pack_e4m3x2(x0.y * inv, x0.x * inv) |
             ((uint32_t)pack_e4m3x2(x0.w * inv, x0.z * inv) << 16);
    outv.y = (uint32_t)pack_e4m3x2(x1.y * inv, x1.x * inv) |
             ((uint32_t)pack_e4m3x2(x1.w * inv, x1.z * inv) << 16);
    outv.z = (uint32_t)pack_e4m3x2(x2.y * inv, x2.x * inv) |
             ((uint32_t)pack_e4m3x2(x2.w * inv, x2.z * inv) << 16);
    outv.w = (uint32_t)pack_e4m3x2(x3.y * inv, x3.x * inv) |
             ((uint32_t)pack_e4m3x2(x3.w * inv, x3.z * inv) << 16);
    reinterpret_cast<uint4*>(g_zn8 + (size_t)row * Dd)[lane] = outv;
    if (lane == 0) g_rowsum[row] = 0.0f;
}

// ============================ kernel 2: symmetric Gram + sum-exp (fp8) ============================
// One CTA per block pair (bi >= bj). 128 threads = 4 warps in 2x2; warp tile 64x64.
// occ 2 (256-reg budget). Fragments double-buffered across the two kk halves so
// LDSM of kk=1 overlaps the MMAs of kk=0.
__global__ __launch_bounds__(128, 2) void simclr_main_kernel() {
    extern __shared__ char smem[];
    const uint32_t sbase = smem_u32(smem);
    float* srow = reinterpret_cast<float*>(smem + SROW_OFF);
    float* scol = reinterpret_cast<float*>(smem + SCOL_OFF);

    const int tid = threadIdx.x;
    const int wid = tid >> 5;
    const int lane = tid & 31;
    const int wr = wid >> 1;        // warp row 0..1
    const int wc = wid & 1;         // warp col 0..1
    const int g = lane >> 2;        // accum row group
    const int tg = lane & 3;        // accum col group

    // linear pair index -> (bi, bj), bj <= bi
    int p = blockIdx.x;
    int bi = (int)((sqrtf(8.0f * (float)p + 1.0f) - 1.0f) * 0.5f);
    while ((bi + 1) * (bi + 2) / 2 <= p) bi++;
    while (bi * (bi + 1) / 2 > p) bi--;
    int bj = p - bi * (bi + 1) / 2;

    const int arow0 = bi * 128;
    const int brow0 = bj * 128;

    srow[tid] = 0.0f;
    scol[tid] = 0.0f;

    // -------- cp.async stage loader: 1024 x 16B per stage, 8 per thread --------
    auto issue_stage = [&](int stage, int k0) {
        #pragma unroll
        for (int i = 0; i < 8; i++) {
            int idx = tid + (i << 7);
            int tile = idx >> 9;                 // 0 = A, 1 = B
            int r = (idx >> 2) & 127;
            int s = idx & 3;
            int grow = (tile ? brow0 : arow0) + r;
            const uint8_t* gp = g_zn8 + (size_t)grow * Dd + (size_t)(k0 + s * 16);
            uint32_t sd = sbase + (uint32_t)(stage * STAGE_BYTES + tile * TILE_BYTES +
                                             r * LDSB + s * 16);
            cp_async16(sd, gp);
        }
    };

    issue_stage(0, 0);  cp_commit();
    issue_stage(1, BK); cp_commit();
    issue_stage(2, 2 * BK); cp_commit();

    float acc[4][8][4];   // 128 f32 accumulators: 64 rows x 64 cols per warp
    #pragma unroll
    for (int mi = 0; mi < 4; mi++)
        #pragma unroll
        for (int ni = 0; ni < 8; ni++)
            #pragma unroll
            for (int r = 0; r < 4; r++) acc[mi][ni][r] = 0.0f;

    // fragment loader for one kk half
    uint32_t afr[2][4][4];
    uint32_t bfr[2][8][2];
    auto load_frags = [&](int buf, int kk, uint32_t As, uint32_t Bs) {
        #pragma unroll
        for (int mi = 0; mi < 4; mi++) {
            uint32_t addr = As +
                (uint32_t)((wr * 64 + mi * 16 + (lane & 15)) * LDSB +
                           kk * 32 + ((lane >> 4) << 4));
            ldmatrix_x4(afr[buf][mi][0], afr[buf][mi][1], afr[buf][mi][2], afr[buf][mi][3], addr);
        }
        #pragma unroll
        for (int h = 0; h < 4; h++) {
            uint32_t addr = Bs +
                (uint32_t)((wc * 64 + h * 16 + ((lane >> 4) << 3) + (lane & 7)) * LDSB +
                           kk * 32 + (((lane >> 3) & 1) << 4));
            uint32_t r0, r1, r2, r3;
            ldmatrix_x4(r0, r1, r2, r3, addr);
            bfr[buf][2 * h][0] = r0; bfr[buf][2 * h][1] = r1;
            bfr[buf][2 * h + 1][0] = r2; bfr[buf][2 * h + 1][1] = r3;
        }
    };

    // -------- mainloop --------
    #pragma unroll 1
    for (int kt = 0; kt < KITERS; kt++) {
        cp_wait<2>();
        __syncthreads();

        if (kt + 3 < KITERS) issue_stage((kt + 3) % STAGES, (kt + 3) * BK);
        cp_commit();

        const uint32_t As = sbase + (uint32_t)((kt % STAGES) * STAGE_BYTES);
        const uint32_t Bs = As + TILE_BYTES;

        load_frags(0, 0, As, Bs);        // kk=0 fragments
        load_frags(1, 1, As, Bs);        // kk=1 fragments issued before kk=0 MMAs
        #pragma unroll
        for (int kk = 0; kk < 2; kk++) {
            #pragma unroll
            for (int mi = 0; mi < 4; mi++)
                #pragma unroll
                for (int ni = 0; ni < 8; ni++)
                    mma_fp8(acc[mi][ni], afr[kk][mi], bfr[kk][ni]);
        }
    }

    // -------- epilogue: exp + symmetric row/col credit --------
    const bool diag = (bi == bj);
    const bool posTile = (bi - bj == 32);
    float csum[8][2];
    #pragma unroll
    for (int ni = 0; ni < 8; ni++) { csum[ni][0] = 0.0f; csum[ni][1] = 0.0f; }

    #pragma unroll
    for (int mi = 0; mi < 4; mi++) {
        float rs0 = 0.0f, rs1 = 0.0f;
        int rowt0 = wr * 64 + mi * 16 + g;
        #pragma unroll
        for (int ni = 0; ni < 8; ni++) {
            int colt0 = wc * 64 + ni * 8 + tg * 2;
            #pragma unroll
            for (int r = 0; r < 4; r++) {
                float v = acc[mi][ni][r] * INV_SS_T;
                int rowt = rowt0 + ((r >> 1) << 3);
                int colt = colt0 + (r & 1);
                float e = __expf(v);
                if (diag && rowt == colt) e = 0.0f;
                if (posTile && rowt == colt) {
                    g_pos[arow0 + rowt] = v;
                    g_pos[brow0 + colt] = v;
                }
                if (r >> 1) rs1 += e; else rs0 += e;
                csum[ni][r & 1] += e;
            }
        }
        rs0 += __shfl_xor_sync(0xFFFFFFFFu, rs0, 1);
        rs0 += __shfl_xor_sync(0xFFFFFFFFu, rs0, 2);
        rs1 += __shfl_xor_sync(0xFFFFFFFFu, rs1, 1);
        rs1 += __shfl_xor_sync(0xFFFFFFFFu, rs1, 2);
        if (tg == 0) {
            atomicAdd(&srow[rowt0], rs0);
            atomicAdd(&srow[rowt0 + 8], rs1);
        }
    }
    if (!diag) {
        #pragma unroll
        for (int ni = 0; ni < 8; ni++)
            #pragma unroll
            for (int par = 0; par < 2; par++) {
                float c = csum[ni][par];
                c += __shfl_xor_sync(0xFFFFFFFFu, c, 4);
                c += __shfl_xor_sync(0xFFFFFFFFu, c, 8);
                c += __shfl_xor_sync(0xFFFFFFFFu, c, 16);
                if (g == 0) atomicAdd(&scol[wc * 64 + ni * 8 + tg * 2 + par], c);
            }
    }

    __syncthreads();
    atomicAdd(&g_rowsum[arow0 + tid], srow[tid]);
    if (!diag) atomicAdd(&g_rowsum[brow0 + tid], scol[tid]);
}

// ============================ kernel 3: finalize ============================
__global__ __launch_bounds__(1024) void finalize_kernel(float* __restrict__ out) {
    int t = threadIdx.x;
    double acc = 0.0;
    for (int i = t; i < Nn; i += 1024)
        acc += (double)(logf(g_rowsum[i]) - g_pos[i]);
    __shared__ double s[1024];
    s[t] = acc;
    __syncthreads();
    for (int o = 512; o > 0; o >>= 1) {
        if (t < o) s[t] += s[t + o];
        __syncthreads();
    }
    if (t == 0) out[0] = (float)(s[0] / (double)Nn);
}

// ============================ launch ============================
extern "C" void kernel_launch(void* const* d_in, const int* in_sizes, int n_in,
                              void* d_out, int out_size) {
    (void)in_sizes; (void)n_in; (void)out_size;
    const float* zi = (const float*)d_in[0];
    const float* zj = (const float*)d_in[1];
    float* out = (float*)d_out;

    static int smem_set = 0;
    if (!smem_set) {
        cudaFuncSetAttribute(simclr_main_kernel,
                             cudaFuncAttributeMaxDynamicSharedMemorySize, SMEM_BYTES);
        smem_set = 1;
    }

    normalize_kernel<<<Nn / 8, 256>>>(zi, zj);
    simclr_main_kernel<<<NPAIRS, 128, SMEM_BYTES>>>();
    finalize_kernel<<<1, 1024>>>(out);
}